// round 3
// baseline (speedup 1.0000x reference)
#include <cuda_runtime.h>
#include <math.h>
#include <stdint.h>

// Problem constants
#define BHALF 8192            // B
#define N     16384           // 2B
#define TILE  128
#define NT    (N / TILE)      // 128 tiles
#define NTRI  (NT * (NT + 1) / 2)        // 8256 triangular blocks
#define NRED  65                          // 64 rowlog reducers + 1 prosody
#define EXPDIAG 7.389056098930650f       // exp(2) = exp(sim_ii / T)
#define NEG_INV_C (-0.34657359027997264f) // -1/(2*log2(e)) = -ln2/2
#define TEMP_EPS 0.01f

// Scratch (deterministic: every slot has exactly one writer)
__device__ float g_part[NT * N];          // 8 MB partial row sums (L2-resident)
__device__ float g_blocksum[64];          // per-reducer log-denominator sums
__device__ float g_tail;                  // prosody + positives tail sum
__device__ int   g_ticket = 0;            // phase-1 completion counter
__device__ int   g_done2  = 0;            // phase-2 completion counter

// Fused 2-pair body: diff, abs, scale, bit-hack rcp + 2 Newton, ex2, accumulate.
// One asm block so ptxas allocates register pairs without boundary MOVs.
// rip = packed (ri, ri); rjn = packed (-rj0, -rj1); cN = (-1/C, -1/C); two2 = (2,2)
__device__ __forceinline__ void pair2_body(
    unsigned long long rip, unsigned long long rjn,
    unsigned long long cN, unsigned long long two2,
    unsigned long long& rowP, unsigned long long& colP)
{
    asm volatile(
        "{\n\t"
        ".reg .b64 df, sn, r, t, e2;\n\t"
        ".reg .b32 bl, bh, rl, rh;\n\t"
        ".reg .f32 fl, fh, el, eh;\n\t"
        "add.rn.f32x2 df, %2, %3;\n\t"                 // ri - rj (both halves)
        "and.b64 df, df, 0x7FFFFFFF7FFFFFFF;\n\t"      // |.| per half
        "fma.rn.f32x2 sn, df, %4, %4;\n\t"             // -(1+d)/C  (negative)
        "mov.b64 {bl, bh}, sn;\n\t"
        "sub.u32 rl, 0xFEF311C3, bl;\n\t"              // magic rcp seed (positive)
        "sub.u32 rh, 0xFEF311C3, bh;\n\t"
        "mov.b64 r, {rl, rh};\n\t"
        "fma.rn.f32x2 t, sn, r, %5;\n\t"               // 2 - |s|r
        "mul.rn.f32x2 r, r, t;\n\t"
        "fma.rn.f32x2 t, sn, r, %5;\n\t"
        "mul.rn.f32x2 r, r, t;\n\t"                    // ~ C/(1+d), rel err ~1e-6
        "mov.b64 {fl, fh}, r;\n\t"
        "ex2.approx.ftz.f32 el, fl;\n\t"
        "ex2.approx.ftz.f32 eh, fh;\n\t"
        "mov.b64 e2, {el, eh};\n\t"
        "add.rn.f32x2 %0, %0, e2;\n\t"
        "add.rn.f32x2 %1, %1, e2;\n\t"
        "}"
        : "+l"(rowP), "+l"(colP)
        : "l"(rip), "l"(rjn), "l"(cN), "l"(two2));
}

__device__ __forceinline__ unsigned long long pk2(float lo, float hi) {
    unsigned long long r;
    asm("mov.b64 %0, {%1, %2};" : "=l"(r) : "f"(lo), "f"(hi));
    return r;
}
__device__ __forceinline__ float lo2(unsigned long long v) {
    float f; asm("{ .reg .f32 t; mov.b64 {%0, t}, %1; }" : "=f"(f) : "l"(v)); return f;
}
__device__ __forceinline__ float hi2(unsigned long long v) {
    float f; asm("{ .reg .f32 t; mov.b64 {t, %0}, %1; }" : "=f"(f) : "l"(v)); return f;
}

// ---------------------------------------------------------------------------
// Single fused kernel. Phase 1: symmetric 128x128 tiles over the triangular
// grid. Phase 2 (last 65 blocks by finish-ticket): row-log reduction (64
// blocks x 256 rows) + prosody/positives tail (1 block). Phase 3 (last
// phase-2 finisher): combine 65 values, write out, reset counters.
// ---------------------------------------------------------------------------
__global__ __launch_bounds__(256, 3) void fused_kernel(
    const float* __restrict__ emb_i, const float* __restrict__ emb_j,
    const float* __restrict__ pro_i, const float* __restrict__ pro_j,
    float* __restrict__ out)
{
    __shared__ float ra[TILE];
    __shared__ float rbn[TILE];           // negated b-tile values
    __shared__ float red[16][TILE + 1];
    __shared__ int   s_ticket;

    const int t = threadIdx.x;

    // ---- decode triangular (a, b) from linear block id ----
    const int k = blockIdx.x;
    float disc = (float)((2 * NT + 1) * (2 * NT + 1) - 8 * k);
    int a = (int)(((float)(2 * NT + 1) - sqrtf(disc)) * 0.5f);
    a = max(0, min(a, NT - 1));
    while (a > 0 && k < a * NT - (a * (a - 1)) / 2) a--;
    while (k >= (a + 1) * NT - ((a + 1) * a) / 2) a++;
    const int b = a + (k - (a * NT - (a * (a - 1)) / 2));

    // ---- load rep values ----
    if (t < TILE) {
        int g = a * TILE + t;
        ra[t] = (g < BHALF) ? emb_i[g] : emb_j[g - BHALF];
    } else {
        int t2 = t - TILE;
        int g = b * TILE + t2;
        float v = (g < BHALF) ? emb_i[g] : emb_j[g - BHALF];
        rbn[t2] = -v;
    }
    __syncthreads();

    const int tx = t & 15;
    const int ty = t >> 4;

    unsigned long long riP[8], rjn[4];
#pragma unroll
    for (int y = 0; y < 8; y++) { float v = ra[ty * 8 + y]; riP[y] = pk2(v, v); }
#pragma unroll
    for (int x2 = 0; x2 < 4; x2++)
        rjn[x2] = pk2(rbn[tx * 8 + 2 * x2], rbn[tx * 8 + 2 * x2 + 1]);

    const unsigned long long cN   = pk2(NEG_INV_C, NEG_INV_C);
    const unsigned long long two2 = pk2(2.0f, 2.0f);

    unsigned long long rowP[8], colP[4];
#pragma unroll
    for (int y = 0; y < 8; y++) rowP[y] = 0ULL;
#pragma unroll
    for (int x2 = 0; x2 < 4; x2++) colP[x2] = 0ULL;

#pragma unroll
    for (int y = 0; y < 8; y++) {
        const unsigned long long rip = riP[y];
#pragma unroll
        for (int x2 = 0; x2 < 4; x2++)
            pair2_body(rip, rjn[x2], cN, two2, rowP[y], colP[x2]);
    }

    // ---- deterministic row-partial reduction (across 16 thread-cols) ----
#pragma unroll
    for (int y = 0; y < 8; y++)
        red[tx][ty * 8 + y] = lo2(rowP[y]) + hi2(rowP[y]);
    __syncthreads();
    if (t < TILE) {
        float s = 0.0f;
#pragma unroll
        for (int kk = 0; kk < 16; kk++) s += red[kk][t];
        g_part[b * N + a * TILE + t] = s;
    }
    __syncthreads();

    // ---- deterministic col-partial reduction (across 16 thread-rows) ----
#pragma unroll
    for (int x2 = 0; x2 < 4; x2++) {
        red[ty][tx * 8 + 2 * x2]     = lo2(colP[x2]);
        red[ty][tx * 8 + 2 * x2 + 1] = hi2(colP[x2]);
    }
    __syncthreads();
    if (a != b && t < TILE) {
        float s = 0.0f;
#pragma unroll
        for (int kk = 0; kk < 16; kk++) s += red[kk][t];
        g_part[a * N + b * TILE + t] = s;
    }

    // ================= phase transition: ticket =================
    __threadfence();
    __syncthreads();
    if (t == 0) s_ticket = atomicAdd(&g_ticket, 1);
    __syncthreads();
    const int ticket = s_ticket;
    if (ticket < NTRI - NRED) return;       // most blocks exit here

    // spin until all tile work is globally visible
    if (t == 0) {
        while (*(volatile int*)&g_ticket != NTRI) { __nanosleep(64); }
    }
    __syncthreads();
    __threadfence();

    const int role = ticket - (NTRI - NRED);   // 0..64

    // reuse red[] as a 256-float reduction scratch
    float* sred = &red[0][0];

    if (role < 64) {
        // ---- row-log reduction: rows [role*256, role*256+256) ----
        const int i = role * 256 + t;
        float s = 0.0f;
#pragma unroll 16
        for (int kk = 0; kk < NT; kk++) s += g_part[kk * N + i];
        float l = logf(s - EXPDIAG);          // remove diagonal term exp(2)
        sred[t] = l;
        __syncthreads();
        for (int off = 128; off > 0; off >>= 1) {
            if (t < off) sred[t] += sred[t + off];
            __syncthreads();
        }
        if (t == 0) g_blocksum[role] = sred[0];
    } else {
        // ---- prosody softmax + positives tail ----
        float mx = -1.0f;
        for (int bb = t; bb < BHALF; bb += 256)
            mx = fmaxf(mx, fabsf(pro_i[bb] - pro_j[bb]));
        sred[t] = mx;
        __syncthreads();
        for (int off = 128; off > 0; off >>= 1) {
            if (t < off) sred[t] = fmaxf(sred[t], sred[t + off]);
            __syncthreads();
        }
        mx = sred[0];
        __syncthreads();

        float se = 0.0f;
        for (int bb = t; bb < BHALF; bb += 256)
            se += expf(fabsf(pro_i[bb] - pro_j[bb]) - mx);
        sred[t] = se;
        __syncthreads();
        for (int off = 128; off > 0; off >>= 1) {
            if (t < off) sred[t] += sred[t + off];
            __syncthreads();
        }
        float invZ = 1.0f / sred[0];
        __syncthreads();

        float lp = 0.0f;
        for (int bb = t; bb < BHALF; bb += 256) {
            float pdv = fabsf(pro_i[bb] - pro_j[bb]);
            lp += logf(expf(pdv - mx) * invZ + TEMP_EPS);
            lp += log1pf(fabsf(emb_i[bb] - emb_j[bb]));
        }
        sred[t] = lp;
        __syncthreads();
        for (int off = 128; off > 0; off >>= 1) {
            if (t < off) sred[t] += sred[t + off];
            __syncthreads();
        }
        if (t == 0) g_tail = sred[0];
    }

    // ================= final combine by last reducer =================
    __threadfence();
    __syncthreads();
    if (t == 0) {
        int old = atomicAdd(&g_done2, 1);
        if (old == NRED - 1) {
            __threadfence();
            float L1 = 0.0f;
            for (int kk = 0; kk < 64; kk++) L1 += g_blocksum[kk];
            out[0] = (L1 + 2.0f * g_tail) / (float)N;
            // reset counters for the next graph replay
            g_ticket = 0;
            g_done2 = 0;
        }
    }
}

// ---------------------------------------------------------------------------
extern "C" void kernel_launch(void* const* d_in, const int* in_sizes, int n_in,
                              void* d_out, int out_size)
{
    const float* emb_i = (const float*)d_in[0];
    const float* emb_j = (const float*)d_in[1];
    const float* pro_i = (const float*)d_in[2];
    const float* pro_j = (const float*)d_in[3];
    float* out = (float*)d_out;

    fused_kernel<<<NTRI, 256>>>(emb_i, emb_j, pro_i, pro_j, out);
}

// round 4
// speedup vs baseline: 1.2004x; 1.2004x over previous
#include <cuda_runtime.h>
#include <math.h>
#include <stdint.h>

// Problem constants
#define BHALF 8192            // B
#define N     16384           // 2B
#define TILE  128
#define NT    (N / TILE)      // 128 tiles
#define NTRI  (NT * (NT + 1) / 2)        // 8256 triangular blocks
#define EXPDIAG 7.389056098930650f       // exp(2) = exp(sim_ii / T)
#define NEG_INV_C (-0.34657359027997264f) // -1/(2*log2(e)) = -ln2/2
#define TEMP_EPS 0.01f

// Scratch (deterministic: every slot has exactly one writer)
__device__ float g_part[NT * N];          // 8 MB partial row sums (L2-resident)
__device__ float g_blocksum[64];
__device__ float g_tail;

// ---------------- packed f32x2 helpers (sm_100 family) ----------------
__device__ __forceinline__ unsigned long long pk2(float lo, float hi) {
    unsigned long long r;
    asm("mov.b64 %0, {%1, %2};" : "=l"(r) : "f"(lo), "f"(hi));
    return r;
}
__device__ __forceinline__ float lo2(unsigned long long v) {
    float f; asm("{ .reg .f32 t; mov.b64 {%0, t}, %1; }" : "=f"(f) : "l"(v)); return f;
}
__device__ __forceinline__ float hi2(unsigned long long v) {
    float f; asm("{ .reg .f32 t; mov.b64 {t, %0}, %1; }" : "=f"(f) : "l"(v)); return f;
}
__device__ __forceinline__ unsigned long long add2(unsigned long long a, unsigned long long b) {
    unsigned long long r;
    asm("add.rn.f32x2 %0, %1, %2;" : "=l"(r) : "l"(a), "l"(b));
    return r;
}
__device__ __forceinline__ unsigned long long mul2(unsigned long long a, unsigned long long b) {
    unsigned long long r;
    asm("mul.rn.f32x2 %0, %1, %2;" : "=l"(r) : "l"(a), "l"(b));
    return r;
}
__device__ __forceinline__ unsigned long long fma2(unsigned long long a, unsigned long long b,
                                                   unsigned long long c) {
    unsigned long long r;
    asm("fma.rn.f32x2 %0, %1, %2, %3;" : "=l"(r) : "l"(a), "l"(b), "l"(c));
    return r;
}
__device__ __forceinline__ float ex2a(float x) {
    float r;
    asm("ex2.approx.ftz.f32 %0, %1;" : "=f"(r) : "f"(x));
    return r;
}

// ---------------------------------------------------------------------------
// Kernel A: symmetric tile kernel (identical to the proven 56.8us version).
// Per 2 pairs: 8 fma-pipe ops + 4 alu + 2 MUFU.EX2 — fma & MUFU co-bound.
// ---------------------------------------------------------------------------
__global__ __launch_bounds__(256, 2) void tile_kernel(
    const float* __restrict__ emb_i, const float* __restrict__ emb_j)
{
    // decode triangular (a, b) from linear block id
    const int k = blockIdx.x;
    float disc = (float)((2 * NT + 1) * (2 * NT + 1) - 8 * k);
    int a = (int)(((float)(2 * NT + 1) - sqrtf(disc)) * 0.5f);
    a = max(0, min(a, NT - 1));
    while (a > 0 && k < a * NT - (a * (a - 1)) / 2) a--;
    while (k >= (a + 1) * NT - ((a + 1) * a) / 2) a++;
    const int b = a + (k - (a * NT - (a * (a - 1)) / 2));

    __shared__ float ra[TILE];
    __shared__ float rbn[TILE];           // NEGATED b-tile values
    __shared__ float red[16][TILE + 1];

    const int t = threadIdx.x;

    if (t < TILE) {
        int g = a * TILE + t;
        ra[t] = (g < BHALF) ? emb_i[g] : emb_j[g - BHALF];
    } else {
        int t2 = t - TILE;
        int g = b * TILE + t2;
        float v = (g < BHALF) ? emb_i[g] : emb_j[g - BHALF];
        rbn[t2] = -v;
    }
    __syncthreads();

    const int tx = t & 15;
    const int ty = t >> 4;

    unsigned long long riP[8], rjn[4];
#pragma unroll
    for (int y = 0; y < 8; y++) { float v = ra[ty * 8 + y]; riP[y] = pk2(v, v); }
#pragma unroll
    for (int x2 = 0; x2 < 4; x2++)
        rjn[x2] = pk2(rbn[tx * 8 + 2 * x2], rbn[tx * 8 + 2 * x2 + 1]);

    const unsigned long long cN   = pk2(NEG_INV_C, NEG_INV_C);
    const unsigned long long two2 = pk2(2.0f, 2.0f);

    unsigned long long rowP[8], colP[4];
#pragma unroll
    for (int y = 0; y < 8; y++) rowP[y] = 0ULL;
#pragma unroll
    for (int x2 = 0; x2 < 4; x2++) colP[x2] = 0ULL;

#pragma unroll
    for (int y = 0; y < 8; y++) {
        const unsigned long long rip = riP[y];
#pragma unroll
        for (int x2 = 0; x2 < 4; x2++) {
            unsigned long long df = add2(rip, rjn[x2]);              // ri - rj
            df &= 0x7FFFFFFF7FFFFFFFULL;                              // |.| per half
            unsigned long long sn = fma2(df, cN, cN);                 // -(1+d)/C
            uint32_t bl = (uint32_t)sn;
            uint32_t bh = (uint32_t)(sn >> 32);
            unsigned long long r = pk2(__uint_as_float(0xFEF311C3u - bl),
                                       __uint_as_float(0xFEF311C3u - bh));
            unsigned long long tt = fma2(sn, r, two2);                // 2 - |s|r
            r = mul2(r, tt);
            tt = fma2(sn, r, two2);
            r = mul2(r, tt);                                          // ~ C/(1+d)
            unsigned long long e2 = pk2(ex2a(lo2(r)), ex2a(hi2(r)));
            rowP[y]  = add2(rowP[y],  e2);
            colP[x2] = add2(colP[x2], e2);
        }
    }

    // --- deterministic row-partial reduction (across the 16 thread-cols) ---
#pragma unroll
    for (int y = 0; y < 8; y++)
        red[tx][ty * 8 + y] = lo2(rowP[y]) + hi2(rowP[y]);
    __syncthreads();
    if (t < TILE) {
        float s = 0.0f;
#pragma unroll
        for (int kk = 0; kk < 16; kk++) s += red[kk][t];
        g_part[b * N + a * TILE + t] = s;
    }
    __syncthreads();

    // --- deterministic col-partial reduction (across the 16 thread-rows) ---
#pragma unroll
    for (int x2 = 0; x2 < 4; x2++) {
        red[ty][tx * 8 + 2 * x2]     = lo2(colP[x2]);
        red[ty][tx * 8 + 2 * x2 + 1] = hi2(colP[x2]);
    }
    __syncthreads();
    if (a != b && t < TILE) {
        float s = 0.0f;
#pragma unroll
        for (int kk = 0; kk < 16; kk++) s += red[kk][t];
        g_part[a * N + b * TILE + t] = s;
    }
}

// ---------------------------------------------------------------------------
// Kernel B: 65 blocks x 256 threads.
//   blocks 0..63 : per-row denominator -> __logf -> block sum  (256 rows each)
//   block 64     : prosody softmax + positives tail (fast intrinsics)
// ---------------------------------------------------------------------------
__global__ __launch_bounds__(256) void reduce_kernel(
    const float* __restrict__ emb_i, const float* __restrict__ emb_j,
    const float* __restrict__ pro_i, const float* __restrict__ pro_j)
{
    __shared__ float sred[256];
    __shared__ float pd[BHALF / 4];   // unused by rowlog blocks; 8KB chunk cache
    const int t = threadIdx.x;
    const int role = blockIdx.x;

    if (role < 64) {
        // ---- row-log reduction: rows [role*256, role*256+256) ----
        const int i = role * 256 + t;
        float s = 0.0f;
#pragma unroll 16
        for (int kk = 0; kk < NT; kk++) s += g_part[kk * N + i];
        sred[t] = __logf(s - EXPDIAG);        // remove diagonal term exp(2)
        __syncthreads();
        for (int off = 128; off > 0; off >>= 1) {
            if (t < off) sred[t] += sred[t + off];
            __syncthreads();
        }
        if (t == 0) g_blocksum[role] = sred[0];
        return;
    }

    // ---- prosody softmax + positives tail (block 64) ----
    // pass 1: max of |pi - pj|
    float mx = -1.0f;
    for (int bb = t; bb < BHALF; bb += 256)
        mx = fmaxf(mx, fabsf(pro_i[bb] - pro_j[bb]));
    sred[t] = mx;
    __syncthreads();
    for (int off = 128; off > 0; off >>= 1) {
        if (t < off) sred[t] = fmaxf(sred[t], sred[t + off]);
        __syncthreads();
    }
    mx = sred[0];
    __syncthreads();

    // pass 2: Z = sum exp(pd - mx)
    float se = 0.0f;
    for (int bb = t; bb < BHALF; bb += 256)
        se += __expf(fabsf(pro_i[bb] - pro_j[bb]) - mx);
    sred[t] = se;
    __syncthreads();
    for (int off = 128; off > 0; off >>= 1) {
        if (t < off) sred[t] += sred[t + off];
        __syncthreads();
    }
    const float invZ = 1.0f / sred[0];
    __syncthreads();

    // pass 3: sum log(softmax + eps) + log1p(|ei - ej|)
    float lp = 0.0f;
    for (int bb = t; bb < BHALF; bb += 256) {
        float pdv = fabsf(pro_i[bb] - pro_j[bb]);
        lp += __logf(__expf(pdv - mx) * invZ + TEMP_EPS);
        lp += __logf(1.0f + fabsf(emb_i[bb] - emb_j[bb]));
    }
    sred[t] = lp;
    __syncthreads();
    for (int off = 128; off > 0; off >>= 1) {
        if (t < off) sred[t] += sred[t + off];
        __syncthreads();
    }
    if (t == 0) g_tail = sred[0];
    (void)pd;
}

// ---------------------------------------------------------------------------
// Kernel C: final combine. 1 block, 64 threads.
// loss = (1/n) [ sum_i log(denom_i) + 2 * tail ]
// ---------------------------------------------------------------------------
__global__ __launch_bounds__(64) void combine_kernel(float* __restrict__ out)
{
    __shared__ float sred[64];
    const int t = threadIdx.x;
    sred[t] = g_blocksum[t];
    __syncthreads();
    for (int off = 32; off > 0; off >>= 1) {
        if (t < off) sred[t] += sred[t + off];
        __syncthreads();
    }
    if (t == 0) out[0] = (sred[0] + 2.0f * g_tail) / (float)N;
}

// ---------------------------------------------------------------------------
extern "C" void kernel_launch(void* const* d_in, const int* in_sizes, int n_in,
                              void* d_out, int out_size)
{
    const float* emb_i = (const float*)d_in[0];
    const float* emb_j = (const float*)d_in[1];
    const float* pro_i = (const float*)d_in[2];
    const float* pro_j = (const float*)d_in[3];
    float* out = (float*)d_out;

    tile_kernel<<<NTRI, 256>>>(emb_i, emb_j);
    reduce_kernel<<<65, 256>>>(emb_i, emb_j, pro_i, pro_j);
    combine_kernel<<<1, 64>>>(out);
}